// round 5
// baseline (speedup 1.0000x reference)
#include <cuda_runtime.h>
#include <cuda_bf16.h>

// SimpleRNN: h_t = tanh(a*x_t + b*h_{t-1} + c), output h_T per row (B=8192, T=4096).
//
// R4: the R3 profile showed runtime ~ proportional to LDG count, i.e. the kernel
// is L1tex-WAVEFRONT bound: per-thread row reads are fully uncoalesced (rows are
// 16KB apart -> 32 lines per LDG = 32 wavefronts). Fix: warp-cooperative staging.
// Each 1-warp CTA owns 32 rows; load phase is coalesced per-row (lanes read
// consecutive t), ~100 wavefronts total vs ~1440. Chain then runs from smem
// (stride 369 -> bank-conflict-free).
// K (truncation, |b|^K<=1e-5) and Kt (exact tail sizing for tanh.approx damping)
// unchanged from R3 — outputs are bit-converged under contraction, so rel_err
// must remain identical.

#define RNN_T 4096
#define KMAX  368          // smem row capacity; fallback to direct path beyond
#define KSTR  369          // smem stride: gcd(369 mod 32, 32) = gcd(17,32) = 1

__device__ __forceinline__ float ex2_approx(float x) {
    float y; asm("ex2.approx.f32 %0, %1;" : "=f"(y) : "f"(x)); return y;
}
__device__ __forceinline__ float rcp_approx(float x) {
    float y; asm("rcp.approx.f32 %0, %1;" : "=f"(y) : "f"(x)); return y;
}
__device__ __forceinline__ float tanh_approx(float x) {
    float y; asm("tanh.approx.f32 %0, %1;" : "=f"(y) : "f"(x)); return y;
}

// Serial chain: Ka approx steps (FFMA+MUFU.TANH, 20 cyc) then exact tail
// (r-formulation, FFMA+EX2+FADD+RCP, 40 cyc). Inlined for both smem and gmem.
__device__ __forceinline__ float run_chain(const float* __restrict__ xr,
                                           int K, int Ka,
                                           float a, float b, float c) {
    float h = 0.0f;
    int t = 0;
#pragma unroll 16
    for (; t < Ka; t++) {
        float w = fmaf(xr[t], a, c);        // off the serial chain
        h = tanh_approx(fmaf(b, h, w));
    }
    const float L2 = 2.0f * 1.4426950408889634f;   // 2*log2(e)
    const float A2 = L2 * a;
    const float C2 = L2 * (b + c);
    const float M  = -2.0f * L2 * b;
    float rr = fmaf(-0.5f, h, 0.5f);        // h -> r = (1-h)/2
#pragma unroll 8
    for (; t < K; t++) {
        float w = fmaf(xr[t], A2, C2);      // off the serial chain
        float z = fmaf(M, rr, w);
        rr = rcp_approx(ex2_approx(z) + 1.0f);
    }
    return fmaf(-2.0f, rr, 1.0f);           // h_T = 1 - 2*r
}

__global__ void __launch_bounds__(32)
simple_rnn_kernel(const float* __restrict__ x,
                  const float* __restrict__ w_ih,
                  const float* __restrict__ w_hh,
                  const float* __restrict__ b_ih,
                  const float* __restrict__ b_hh,
                  float* __restrict__ out,
                  int B) {
    __shared__ float sm[32 * KSTR];         // 47,232 B

    const int lane = threadIdx.x;
    const int base = blockIdx.x * 32;

    const float a = w_ih[0];
    const float b = w_hh[0];
    const float c = b_ih[0] + b_hh[0];

    // ---- horizons (uniform across all threads) ----
    float ab = fabsf(b);
    float l  = __logf(ab);                  // < 0 for |b| < 1
    int K, Kt;
    if (!(l < -1e-9f)) {                    // |b| >= 1 / degenerate: full exact
        K = RNN_T; Kt = RNN_T;
    } else {
        float inv = 1.0f / (-l);
        float kf = 11.513f * inv;           // |b|^K <= 1e-5
        K = (kf >= (float)RNN_T) ? RNN_T : (int)kf + 1;
        float kt = __logf(5.0f / (1.0f - ab)) * inv;  // damp tanh.approx error
        Kt = (kt >= (float)K) ? K : (int)kt + 1;
    }
    if (K  < 1) K  = 1;
    if (Kt < 1) Kt = 1;
    if (Kt > K) Kt = K;
    const int Ka    = K - Kt;
    const int start = RNN_T - K;

    if (K <= KMAX) {
        // ---- coalesced staging: 32 rows, lanes read consecutive t ----
#pragma unroll 4
        for (int j = 0; j < 32; j++) {
            int row = base + j;
            if (row < B) {
                const float* __restrict__ rp = x + (size_t)row * RNN_T + start;
                for (int t = lane; t < K; t += 32)
                    sm[j * KSTR + t] = rp[t];
            }
        }
        __syncwarp();

        int r = base + lane;
        if (r < B)
            out[r] = run_chain(&sm[lane * KSTR], K, Ka, a, b, c);
    } else {
        // ---- rare fallback (|b| > 0.969): direct per-thread loads ----
        int r = base + lane;
        if (r < B) {
            const float* __restrict__ xr = x + (size_t)r * RNN_T + start;
            out[r] = run_chain(xr, K, Ka, a, b, c);
        }
    }
}

extern "C" void kernel_launch(void* const* d_in, const int* in_sizes, int n_in,
                              void* d_out, int out_size) {
    const float* x    = (const float*)d_in[0];
    const float* w_ih = (const float*)d_in[1];
    const float* w_hh = (const float*)d_in[2];
    const float* b_ih = (const float*)d_in[3];
    const float* b_hh = (const float*)d_in[4];
    float* out = (float*)d_out;

    int B = out_size;                   // output is [B, 1] float32
    int blocks = (B + 31) / 32;         // 1 warp per CTA, 32 rows per CTA
    simple_rnn_kernel<<<blocks, 32>>>(x, w_ih, w_hh, b_ih, b_hh, out, B);
}

// round 6
// speedup vs baseline: 2.1470x; 2.1470x over previous
#include <cuda_runtime.h>
#include <cuda_bf16.h>

// SimpleRNN: h_t = tanh(a*x_t + b*h_{t-1} + c), output h_T per row (B=8192, T=4096).
//
// R5 = R3 (best: 8.7us) + two targeted changes:
//  1. float4 row reads (LDG.128): R3 was L1tex-wavefront bound (45 scalar LDGs
//     x 32 lines each = 1440 wavefronts/warp). LDG.128 cuts instructions 4x ->
//     ~320 wavefronts. Loads stay independent inside unrolled quad-loops so
//     ptxas front-batches them (high MLP) — avoids R4's staging-latency trap.
//     Alignment: K and Kt rounded up to multiples of 4 (extra early steps from
//     h=0 only improve accuracy); T=4096 keeps float4 bases 16B-aligned.
//  2. Truncation budget 1e-4 (|b|^K <= 1e-4, K = 9.211/-ln|b|): fewer loads
//     and chain steps. Total error ~2e-4 << 1e-3 gate.

#define RNN_T 4096

__device__ __forceinline__ float ex2_approx(float x) {
    float y; asm("ex2.approx.f32 %0, %1;" : "=f"(y) : "f"(x)); return y;
}
__device__ __forceinline__ float rcp_approx(float x) {
    float y; asm("rcp.approx.f32 %0, %1;" : "=f"(y) : "f"(x)); return y;
}
__device__ __forceinline__ float tanh_approx(float x) {
    float y; asm("tanh.approx.f32 %0, %1;" : "=f"(y) : "f"(x)); return y;
}

__global__ void __launch_bounds__(32)
simple_rnn_kernel(const float* __restrict__ x,
                  const float* __restrict__ w_ih,
                  const float* __restrict__ w_hh,
                  const float* __restrict__ b_ih,
                  const float* __restrict__ b_hh,
                  float* __restrict__ out,
                  int B) {
    int r = blockIdx.x * blockDim.x + threadIdx.x;
    if (r >= B) return;

    const float a = w_ih[0];
    const float b = w_hh[0];
    const float c = b_ih[0] + b_hh[0];

    // ---- horizons (uniform across threads) ----
    float ab = fabsf(b);
    float l  = __logf(ab);                  // < 0 for |b| < 1 (-inf for b==0)
    int K, Kt;
    if (!(l < -1e-9f)) {                    // |b| >= 1 / degenerate: full exact
        K = RNN_T; Kt = RNN_T;
    } else {
        float inv = 1.0f / (-l);
        float kf = 9.211f * inv;            // |b|^K <= 1e-4
        K = (kf >= (float)RNN_T) ? RNN_T : (int)kf + 1;
        float kt = __logf(5.0f / (1.0f - ab)) * inv;  // damp tanh.approx error
        Kt = (kt >= (float)K) ? K : (int)kt + 1;
    }
    if (K  < 1) K  = 1;
    if (Kt < 1) Kt = 1;
    if (Kt > K) Kt = K;

    // round to float4 granularity (extra early steps only improve accuracy)
    int K4  = (K  + 3) & ~3;  if (K4  > RNN_T) K4  = RNN_T;
    int Kt4 = (Kt + 3) & ~3;  if (Kt4 > K4)    Kt4 = K4;
    const int nqa = (K4 - Kt4) >> 2;        // approx-phase quads
    const int nqe = Kt4 >> 2;               // exact-phase quads

    // 16B-aligned: row base is 16KB-aligned, (RNN_T - K4) is a multiple of 4
    const float4* __restrict__ xq =
        (const float4*)(x + (size_t)r * RNN_T + (RNN_T - K4));

    float h = 0.0f;

    // ---- approx phase: h = tanh.approx(b*h + (a*x + c)), 20 cyc/step ----
#pragma unroll 8
    for (int q = 0; q < nqa; q++) {
        float4 v = xq[q];                   // independent of chain -> hoisted
        h = tanh_approx(fmaf(b, h, fmaf(v.x, a, c)));
        h = tanh_approx(fmaf(b, h, fmaf(v.y, a, c)));
        h = tanh_approx(fmaf(b, h, fmaf(v.z, a, c)));
        h = tanh_approx(fmaf(b, h, fmaf(v.w, a, c)));
    }

    // ---- exact tail: r = 1/(exp2(z)+1), h = 1-2r, 40 cyc/step ----
    const float L2 = 2.0f * 1.4426950408889634f;   // 2*log2(e)
    const float A2 = L2 * a;
    const float C2 = L2 * (b + c);
    const float M  = -2.0f * L2 * b;

    float rr = fmaf(-0.5f, h, 0.5f);        // h -> r = (1-h)/2
    const float4* __restrict__ xe = xq + nqa;
#pragma unroll 4
    for (int q = 0; q < nqe; q++) {
        float4 v = xe[q];                   // independent of chain -> hoisted
        float z;
        z = fmaf(M, rr, fmaf(v.x, A2, C2)); rr = rcp_approx(ex2_approx(z) + 1.0f);
        z = fmaf(M, rr, fmaf(v.y, A2, C2)); rr = rcp_approx(ex2_approx(z) + 1.0f);
        z = fmaf(M, rr, fmaf(v.z, A2, C2)); rr = rcp_approx(ex2_approx(z) + 1.0f);
        z = fmaf(M, rr, fmaf(v.w, A2, C2)); rr = rcp_approx(ex2_approx(z) + 1.0f);
    }

    out[r] = fmaf(-2.0f, rr, 1.0f);         // h_T = 1 - 2*r
}

extern "C" void kernel_launch(void* const* d_in, const int* in_sizes, int n_in,
                              void* d_out, int out_size) {
    const float* x    = (const float*)d_in[0];
    const float* w_ih = (const float*)d_in[1];
    const float* w_hh = (const float*)d_in[2];
    const float* b_ih = (const float*)d_in[3];
    const float* b_hh = (const float*)d_in[4];
    float* out = (float*)d_out;

    int B = out_size;                   // output is [B, 1] float32
    int blocks = (B + 31) / 32;         // 1 warp per CTA -> 256 CTAs / 148 SMs
    simple_rnn_kernel<<<blocks, 32>>>(x, w_ih, w_hh, b_ih, b_hh, out, B);
}

// round 7
// speedup vs baseline: 2.2103x; 1.0295x over previous
#include <cuda_runtime.h>
#include <cuda_bf16.h>

// SimpleRNN: h_t = tanh(a*x_t + b*h_{t-1} + c), output h_T per row (B=8192, T=4096).
//
// R6 = R5 structure (float4 loads, hybrid MUFU.TANH chain + exact ex2/rcp tail)
// with tighter error budgets and launch-shape tweak. R5 proved L1tex wavefronts
// are NOT binding (L1 16%->3.6%, time flat); remaining time = first-load
// latency + serial chain + ~5000-cyc launch/drain floor. So: cut steps.
//  1. Truncation |b|^K <= 2.5e-4  -> K = 8.29/-ln|b|   (~10% fewer steps).
//  2. Exact tail sized by 5e-4*|b|^Kt/(1-|b|) <= 2e-4 -> Kt = ln(2.5/(1-|b|))/-ln|b|.
//  3. block=64 (2 warps/CTA, 128 CTAs): fewer CTA dispatches, still no MUFU
//     contention (<=1 resident warp per SMSP on average).
// Worst-case total error ~7e-4 < 1e-3 gate; typical ~3e-4.

#define RNN_T 4096

__device__ __forceinline__ float ex2_approx(float x) {
    float y; asm("ex2.approx.f32 %0, %1;" : "=f"(y) : "f"(x)); return y;
}
__device__ __forceinline__ float rcp_approx(float x) {
    float y; asm("rcp.approx.f32 %0, %1;" : "=f"(y) : "f"(x)); return y;
}
__device__ __forceinline__ float tanh_approx(float x) {
    float y; asm("tanh.approx.f32 %0, %1;" : "=f"(y) : "f"(x)); return y;
}

__global__ void __launch_bounds__(64)
simple_rnn_kernel(const float* __restrict__ x,
                  const float* __restrict__ w_ih,
                  const float* __restrict__ w_hh,
                  const float* __restrict__ b_ih,
                  const float* __restrict__ b_hh,
                  float* __restrict__ out,
                  int B) {
    int r = blockIdx.x * blockDim.x + threadIdx.x;
    if (r >= B) return;

    const float a = w_ih[0];
    const float b = w_hh[0];
    const float c = b_ih[0] + b_hh[0];

    // ---- horizons (uniform across threads) ----
    float ab = fabsf(b);
    float l  = __logf(ab);                  // < 0 for |b| < 1 (-inf for b==0)
    int K, Kt;
    if (!(l < -1e-9f)) {                    // |b| >= 1 / degenerate: full exact
        K = RNN_T; Kt = RNN_T;
    } else {
        float inv = 1.0f / (-l);
        float kf = 8.29f * inv;             // |b|^K <= 2.5e-4
        K = (kf >= (float)RNN_T) ? RNN_T : (int)kf + 1;
        float kt = __logf(2.5f / (1.0f - ab)) * inv;  // |b|^Kt <= 0.4(1-|b|)
        Kt = (kt >= (float)K) ? K : (int)kt + 1;
    }
    if (K  < 1) K  = 1;
    if (Kt < 2) Kt = 2;                     // final steps always exact
    if (Kt > K) Kt = K;

    // round to float4 granularity (extra early steps only improve accuracy)
    int K4  = (K  + 3) & ~3;  if (K4  > RNN_T) K4  = RNN_T;
    int Kt4 = (Kt + 3) & ~3;  if (Kt4 > K4)    Kt4 = K4;
    const int nqa = (K4 - Kt4) >> 2;        // approx-phase quads
    const int nqe = Kt4 >> 2;               // exact-phase quads

    // 16B-aligned: row base is 16KB-aligned, (RNN_T - K4) is a multiple of 4
    const float4* __restrict__ xq =
        (const float4*)(x + (size_t)r * RNN_T + (RNN_T - K4));

    float h = 0.0f;

    // ---- approx phase: h = tanh.approx(b*h + (a*x + c)), 20 cyc/step ----
#pragma unroll 8
    for (int q = 0; q < nqa; q++) {
        float4 v = xq[q];                   // independent of chain -> hoisted
        h = tanh_approx(fmaf(b, h, fmaf(v.x, a, c)));
        h = tanh_approx(fmaf(b, h, fmaf(v.y, a, c)));
        h = tanh_approx(fmaf(b, h, fmaf(v.z, a, c)));
        h = tanh_approx(fmaf(b, h, fmaf(v.w, a, c)));
    }

    // ---- exact tail: r = 1/(exp2(z)+1), h = 1-2r, 40 cyc/step ----
    const float L2 = 2.0f * 1.4426950408889634f;   // 2*log2(e)
    const float A2 = L2 * a;
    const float C2 = L2 * (b + c);
    const float M  = -2.0f * L2 * b;

    float rr = fmaf(-0.5f, h, 0.5f);        // h -> r = (1-h)/2
    const float4* __restrict__ xe = xq + nqa;
#pragma unroll 4
    for (int q = 0; q < nqe; q++) {
        float4 v = xe[q];                   // independent of chain -> hoisted
        float z;
        z = fmaf(M, rr, fmaf(v.x, A2, C2)); rr = rcp_approx(ex2_approx(z) + 1.0f);
        z = fmaf(M, rr, fmaf(v.y, A2, C2)); rr = rcp_approx(ex2_approx(z) + 1.0f);
        z = fmaf(M, rr, fmaf(v.z, A2, C2)); rr = rcp_approx(ex2_approx(z) + 1.0f);
        z = fmaf(M, rr, fmaf(v.w, A2, C2)); rr = rcp_approx(ex2_approx(z) + 1.0f);
    }

    out[r] = fmaf(-2.0f, rr, 1.0f);         // h_T = 1 - 2*r
}

extern "C" void kernel_launch(void* const* d_in, const int* in_sizes, int n_in,
                              void* d_out, int out_size) {
    const float* x    = (const float*)d_in[0];
    const float* w_ih = (const float*)d_in[1];
    const float* w_hh = (const float*)d_in[2];
    const float* b_ih = (const float*)d_in[3];
    const float* b_hh = (const float*)d_in[4];
    float* out = (float*)d_out;

    int B = out_size;                   // output is [B, 1] float32
    int threads = 64;                   // 2 warps/CTA -> 128 CTAs / 148 SMs
    int blocks = (B + threads - 1) / threads;
    simple_rnn_kernel<<<blocks, threads>>>(x, w_ih, w_hh, b_ih, b_hh, out, B);
}

// round 8
// speedup vs baseline: 2.8798x; 1.3029x over previous
#include <cuda_runtime.h>
#include <cuda_bf16.h>

// SimpleRNN: h_t = tanh(a*x_t + b*h_{t-1} + c), output h_T per row (B=8192, T=4096).
//
// R7: break the serial latency ladder. R6 profile model: param loads (~600cyc)
// -> K computation (~80) -> x loads (~700) -> chain (~1000) are SEQUENTIAL
// because the x address depends on K(params). Fix: speculatively load the last
// 64 elements (16 LDG.128, address = f(tid) only) at cycle 0, concurrently
// with the param loads; compute K while everything is in flight; then jump to
// a fully-static unrolled chain instance over the smallest window W in
// {16,32,48,64} >= K4 (extra early steps from h=0 only add accuracy).
// Static exact tails KT={4,8,16,20} bound the worst-case tanh.approx error at
// each instance's max |b| (0.596/0.772/0.841/0.879) to <=3.1e-4; truncation
// budget |b|^K <= 2.5e-4. Total <=5.6e-4 < 1e-3 gate. K4>64 -> R6 dynamic
// fallback (rare: |b|>0.879).

#define RNN_T 4096
#define WQ_MAX 16          // speculative window: 16 float4 = 64 elements

__device__ __forceinline__ float ex2_approx(float x) {
    float y; asm("ex2.approx.f32 %0, %1;" : "=f"(y) : "f"(x)); return y;
}
__device__ __forceinline__ float rcp_approx(float x) {
    float y; asm("rcp.approx.f32 %0, %1;" : "=f"(y) : "f"(x)); return y;
}
__device__ __forceinline__ float tanh_approx(float x) {
    float y; asm("tanh.approx.f32 %0, %1;" : "=f"(y) : "f"(x)); return y;
}

// Fully-static chain over quads [16-NQ, 16) of the register window.
// First (NQ-QT) quads: tanh.approx steps (20 cyc). Last QT quads: exact
// r-formulation steps (40 cyc). All indices compile-time -> v stays in regs.
template<int NQ, int QT>
__device__ __forceinline__ float chain_static(const float4* v,
                                              float a, float b, float c,
                                              float A2, float C2, float M) {
    float h = 0.0f;
#pragma unroll
    for (int q = WQ_MAX - NQ; q < WQ_MAX - QT; q++) {
        float4 t = v[q];
        h = tanh_approx(fmaf(b, h, fmaf(t.x, a, c)));
        h = tanh_approx(fmaf(b, h, fmaf(t.y, a, c)));
        h = tanh_approx(fmaf(b, h, fmaf(t.z, a, c)));
        h = tanh_approx(fmaf(b, h, fmaf(t.w, a, c)));
    }
    float rr = fmaf(-0.5f, h, 0.5f);        // h -> r = (1-h)/2
#pragma unroll
    for (int q = WQ_MAX - QT; q < WQ_MAX; q++) {
        float4 t = v[q];
        float z;
        z = fmaf(M, rr, fmaf(t.x, A2, C2)); rr = rcp_approx(ex2_approx(z) + 1.0f);
        z = fmaf(M, rr, fmaf(t.y, A2, C2)); rr = rcp_approx(ex2_approx(z) + 1.0f);
        z = fmaf(M, rr, fmaf(t.z, A2, C2)); rr = rcp_approx(ex2_approx(z) + 1.0f);
        z = fmaf(M, rr, fmaf(t.w, A2, C2)); rr = rcp_approx(ex2_approx(z) + 1.0f);
    }
    return fmaf(-2.0f, rr, 1.0f);           // h_T = 1 - 2*r
}

__global__ void __launch_bounds__(64)
simple_rnn_kernel(const float* __restrict__ x,
                  const float* __restrict__ w_ih,
                  const float* __restrict__ w_hh,
                  const float* __restrict__ b_ih,
                  const float* __restrict__ b_hh,
                  float* __restrict__ out,
                  int B) {
    int r = blockIdx.x * blockDim.x + threadIdx.x;
    if (r >= B) return;

    // ---- speculative window load: address independent of params ----
    const float4* __restrict__ xw =
        (const float4*)(x + (size_t)r * RNN_T + (RNN_T - 4 * WQ_MAX));
    float4 v[WQ_MAX];
#pragma unroll
    for (int i = 0; i < WQ_MAX; i++) v[i] = xw[i];   // 16 LDG.128, MLP=16

    // ---- param loads (independent; overlap with window loads) ----
    const float a = w_ih[0];
    const float b = w_hh[0];
    const float c = b_ih[0] + b_hh[0];

    // ---- horizon K (overlapped with load latency) ----
    float ab = fabsf(b);
    float l  = __logf(ab);                  // < 0 for |b| < 1 (-inf for b==0)
    int K;
    if (!(l < -1e-9f)) {
        K = RNN_T;                          // |b| >= 1 / degenerate
    } else {
        float kf = 8.29f / (-l);            // |b|^K <= 2.5e-4
        K = (kf >= (float)RNN_T) ? RNN_T : (int)kf + 1;
    }
    if (K < 1) K = 1;
    int K4 = (K + 3) & ~3;

    const float L2 = 2.0f * 1.4426950408889634f;   // 2*log2(e)
    const float A2 = L2 * a;
    const float C2 = L2 * (b + c);
    const float M  = -2.0f * L2 * b;

    // ---- static instances (warp-uniform branch) ----
    if (K4 <= 16) {                         // |b| <= 0.596, tail err <= 1.6e-4
        out[r] = chain_static<4, 1>(v, a, b, c, A2, C2, M);
        return;
    } else if (K4 <= 32) {                  // |b| <= 0.772, tail err <= 2.8e-4
        out[r] = chain_static<8, 2>(v, a, b, c, A2, C2, M);
        return;
    } else if (K4 <= 48) {                  // |b| <= 0.841, tail err <= 2.0e-4
        out[r] = chain_static<12, 4>(v, a, b, c, A2, C2, M);
        return;
    } else if (K4 <= 64) {                  // |b| <= 0.879, tail err <= 3.1e-4
        out[r] = chain_static<16, 5>(v, a, b, c, A2, C2, M);
        return;
    }

    // ---- dynamic fallback (|b| > 0.879): R6 path, loads from gmem ----
    int Kt;
    {
        float inv = 1.0f / (-l);
        float kt = __logf(2.5f / (1.0f - ab)) * inv;
        Kt = (kt >= (float)K) ? K : (int)kt + 1;
        if (l >= -1e-9f) Kt = K;            // |b| >= 1: all exact
    }
    if (Kt < 2) Kt = 2;
    if (Kt > K) Kt = K;
    if (K4 > RNN_T) K4 = RNN_T;
    int Kt4 = (Kt + 3) & ~3;  if (Kt4 > K4) Kt4 = K4;
    const int nqa = (K4 - Kt4) >> 2;
    const int nqe = Kt4 >> 2;

    const float4* __restrict__ xq =
        (const float4*)(x + (size_t)r * RNN_T + (RNN_T - K4));

    float h = 0.0f;
#pragma unroll 8
    for (int q = 0; q < nqa; q++) {
        float4 t = xq[q];
        h = tanh_approx(fmaf(b, h, fmaf(t.x, a, c)));
        h = tanh_approx(fmaf(b, h, fmaf(t.y, a, c)));
        h = tanh_approx(fmaf(b, h, fmaf(t.z, a, c)));
        h = tanh_approx(fmaf(b, h, fmaf(t.w, a, c)));
    }
    float rr = fmaf(-0.5f, h, 0.5f);
    const float4* __restrict__ xe = xq + nqa;
#pragma unroll 4
    for (int q = 0; q < nqe; q++) {
        float4 t = xe[q];
        float z;
        z = fmaf(M, rr, fmaf(t.x, A2, C2)); rr = rcp_approx(ex2_approx(z) + 1.0f);
        z = fmaf(M, rr, fmaf(t.y, A2, C2)); rr = rcp_approx(ex2_approx(z) + 1.0f);
        z = fmaf(M, rr, fmaf(t.z, A2, C2)); rr = rcp_approx(ex2_approx(z) + 1.0f);
        z = fmaf(M, rr, fmaf(t.w, A2, C2)); rr = rcp_approx(ex2_approx(z) + 1.0f);
    }
    out[r] = fmaf(-2.0f, rr, 1.0f);
}

extern "C" void kernel_launch(void* const* d_in, const int* in_sizes, int n_in,
                              void* d_out, int out_size) {
    const float* x    = (const float*)d_in[0];
    const float* w_ih = (const float*)d_in[1];
    const float* w_hh = (const float*)d_in[2];
    const float* b_ih = (const float*)d_in[3];
    const float* b_hh = (const float*)d_in[4];
    float* out = (float*)d_out;

    int B = out_size;                   // output is [B, 1] float32
    int threads = 64;
    int blocks = (B + threads - 1) / threads;
    simple_rnn_kernel<<<blocks, threads>>>(x, w_ih, w_hh, b_ih, b_hh, out, B);
}